// round 1
// baseline (speedup 1.0000x reference)
#include <cuda_runtime.h>
#include <math.h>

// Problem constants
#define BN 4096      // batch
#define IND 2048     // input dim
#define KC 8192      // codes per split
#define DD 256       // embedding dim per split
#define SS 8         // splits
#define SD 2048      // SS*DD

// ---------------- scratch (device globals; no allocation allowed) ----------
__device__ float g_z[BN * SD];          // encoder output z  [4096,2048]  (32MB)
__device__ float g_zsq[BN * SS];        // ||z_bs||^2        [4096,8]
__device__ float g_esq[SS * KC];        // ||e_sk||^2        [8,8192]
__device__ int   g_codes[BN * SS];      // argmin codes
__device__ int   g_counts[SS * KC];     // histogram
__device__ float g_perp[SS];            // per-split perplexity

// ---------------- zero counts each launch (graph-replayed) ------------------
__global__ void zero_counts_kernel() {
    int i = blockIdx.x * blockDim.x + threadIdx.x;
    if (i < SS * KC) g_counts[i] = 0;
}

// ---------------- generic SGEMM: C[m,n] = sum_k A[m,k]*B[n,k] + bias[n] -----
// 128x128 tile, K-step 8, 256 threads, 8x8 microtile.
__global__ __launch_bounds__(256) void sgemm_tn(const float* __restrict__ A,
                                                const float* __restrict__ Bm,
                                                const float* __restrict__ bias,
                                                float* __restrict__ C,
                                                int M, int N, int Kd) {
    __shared__ float As[8][128];
    __shared__ float Bs[8][128];
    const int bm = blockIdx.y * 128;
    const int bn = blockIdx.x * 128;
    const int tid = threadIdx.x;
    const int tx = tid & 15;
    const int ty = tid >> 4;
    const int lrow = tid >> 1;          // 0..127
    const int lc4  = (tid & 1) << 2;    // 0 or 4

    const float* Aptr = A + (size_t)(bm + lrow) * Kd + lc4;
    const float* Bptr = Bm + (size_t)(bn + lrow) * Kd + lc4;

    float acc[8][8];
#pragma unroll
    for (int i = 0; i < 8; i++)
#pragma unroll
        for (int j = 0; j < 8; j++) acc[i][j] = 0.0f;

    for (int k0 = 0; k0 < Kd; k0 += 8) {
        float4 a4 = *(const float4*)(Aptr + k0);
        float4 b4 = *(const float4*)(Bptr + k0);
        __syncthreads();
        As[lc4 + 0][lrow] = a4.x; As[lc4 + 1][lrow] = a4.y;
        As[lc4 + 2][lrow] = a4.z; As[lc4 + 3][lrow] = a4.w;
        Bs[lc4 + 0][lrow] = b4.x; Bs[lc4 + 1][lrow] = b4.y;
        Bs[lc4 + 2][lrow] = b4.z; Bs[lc4 + 3][lrow] = b4.w;
        __syncthreads();
#pragma unroll
        for (int kk = 0; kk < 8; kk++) {
            float a[8], b[8];
            *(float4*)&a[0] = *(const float4*)&As[kk][ty * 4];
            *(float4*)&a[4] = *(const float4*)&As[kk][64 + ty * 4];
            *(float4*)&b[0] = *(const float4*)&Bs[kk][tx * 4];
            *(float4*)&b[4] = *(const float4*)&Bs[kk][64 + tx * 4];
#pragma unroll
            for (int i = 0; i < 8; i++)
#pragma unroll
                for (int j = 0; j < 8; j++) acc[i][j] += a[i] * b[j];
        }
    }
#pragma unroll
    for (int i = 0; i < 8; i++) {
        int r = bm + ((i < 4) ? (ty * 4 + i) : (64 + ty * 4 + (i - 4)));
#pragma unroll
        for (int j = 0; j < 8; j++) {
            int c = bn + ((j < 4) ? (tx * 4 + j) : (64 + tx * 4 + (j - 4)));
            C[(size_t)r * N + c] = acc[i][j] + bias[c];
        }
    }
}

// ---------------- row-wise sum of squares over contiguous 256-chunks --------
__global__ void rowsumsq_kernel(const float* __restrict__ src,
                                float* __restrict__ dst, int nrows) {
    int warp = (blockIdx.x * blockDim.x + threadIdx.x) >> 5;
    int lane = threadIdx.x & 31;
    if (warp >= nrows) return;
    const float* p = src + (size_t)warp * DD;
    float s = 0.0f;
#pragma unroll
    for (int i = 0; i < DD / 32; i++) {
        float v = p[lane + i * 32];
        s += v * v;
    }
#pragma unroll
    for (int o = 16; o; o >>= 1) s += __shfl_xor_sync(0xFFFFFFFFu, s, o);
    if (lane == 0) dst[warp] = s;
}

// ---------------- fused distance + argmin -----------------------------------
// grid = (B/128, S). Block handles 128 rows of one split, scans all K=8192.
// distance_k = fl( fl(z_sq + e_sq_k) - fl(2*cross_k) )  -- mirrors reference.
// Dynamic smem layout: Zs[256][128] | Bsm[8][128] | Es[128]
__global__ __launch_bounds__(256) void dist_argmin_kernel(const float* __restrict__ cb) {
    extern __shared__ float dsm[];
    float* Zs  = dsm;                 // 256*128
    float* Bsm = dsm + DD * 128;      // 8*128
    float* Es  = Bsm + 8 * 128;       // 128

    const int s  = blockIdx.y;
    const int bm = blockIdx.x * 128;
    const int tid = threadIdx.x;
    const int tx = tid & 15;
    const int ty = tid >> 4;
    const int lrow = tid >> 1;
    const int lc4  = (tid & 1) << 2;

    // Load z tile [128 rows x 256 dims] transposed into Zs[d*128+row]
    for (int idx = tid; idx < 128 * 64; idx += 256) {
        int row = idx >> 6;
        int d4  = (idx & 63) << 2;
        float4 v = *(const float4*)(g_z + (size_t)(bm + row) * SD + s * DD + d4);
        Zs[(d4 + 0) * 128 + row] = v.x;
        Zs[(d4 + 1) * 128 + row] = v.y;
        Zs[(d4 + 2) * 128 + row] = v.z;
        Zs[(d4 + 3) * 128 + row] = v.w;
    }

    float zr[8];
#pragma unroll
    for (int i = 0; i < 8; i++) {
        int rl = (i < 4) ? (ty * 4 + i) : (64 + ty * 4 + (i - 4));
        zr[i] = g_zsq[(size_t)(bm + rl) * SS + s];
    }

    float bestd[8];
    int   bidx[8];
#pragma unroll
    for (int i = 0; i < 8; i++) { bestd[i] = INFINITY; bidx[i] = 0; }

    for (int k0 = 0; k0 < KC; k0 += 128) {
        __syncthreads();   // protect Es (prev epilogue readers) before rewrite
        if (tid < 32) {
            float4 e4 = *(const float4*)(g_esq + (size_t)s * KC + k0 + (tid << 2));
            Es[tid * 4 + 0] = e4.x; Es[tid * 4 + 1] = e4.y;
            Es[tid * 4 + 2] = e4.z; Es[tid * 4 + 3] = e4.w;
        }
        float acc[8][8];
#pragma unroll
        for (int i = 0; i < 8; i++)
#pragma unroll
            for (int j = 0; j < 8; j++) acc[i][j] = 0.0f;

        const float* cbase = cb + ((size_t)(s * KC + k0 + lrow)) * DD + lc4;
        for (int kk0 = 0; kk0 < DD; kk0 += 8) {
            float4 b4 = *(const float4*)(cbase + kk0);
            __syncthreads();
            Bsm[(lc4 + 0) * 128 + lrow] = b4.x;
            Bsm[(lc4 + 1) * 128 + lrow] = b4.y;
            Bsm[(lc4 + 2) * 128 + lrow] = b4.z;
            Bsm[(lc4 + 3) * 128 + lrow] = b4.w;
            __syncthreads();
#pragma unroll
            for (int kk = 0; kk < 8; kk++) {
                float a[8], b[8];
                const float* Zrow = Zs + (kk0 + kk) * 128;
                const float* Brow = Bsm + kk * 128;
                *(float4*)&a[0] = *(const float4*)&Zrow[ty * 4];
                *(float4*)&a[4] = *(const float4*)&Zrow[64 + ty * 4];
                *(float4*)&b[0] = *(const float4*)&Brow[tx * 4];
                *(float4*)&b[4] = *(const float4*)&Brow[64 + tx * 4];
#pragma unroll
                for (int i = 0; i < 8; i++)
#pragma unroll
                    for (int j = 0; j < 8; j++) acc[i][j] += a[i] * b[j];
            }
        }
        // epilogue: distances + running argmin (k ascending per thread)
#pragma unroll
        for (int j = 0; j < 8; j++) {
            int cl = (j < 4) ? (tx * 4 + j) : (64 + tx * 4 + (j - 4));
            float e = Es[cl];
            int kg = k0 + cl;
#pragma unroll
            for (int i = 0; i < 8; i++) {
                float t = zr[i] + e;
                float d = t - 2.0f * acc[i][j];
                if (d < bestd[i] || (d == bestd[i] && kg < bidx[i])) {
                    bestd[i] = d; bidx[i] = kg;
                }
            }
        }
    }

    // cross-thread reduction (lexicographic min for first-index tie-break)
    __syncthreads();
    float* redd = Zs;                       // reuse: 128*16 floats
    int*   redi = (int*)(Zs + 128 * 16);    // 128*16 ints
#pragma unroll
    for (int i = 0; i < 8; i++) {
        int rl = (i < 4) ? (ty * 4 + i) : (64 + ty * 4 + (i - 4));
        redd[rl * 16 + tx] = bestd[i];
        redi[rl * 16 + tx] = bidx[i];
    }
    __syncthreads();
    if (tid < 128) {
        float bd = redd[tid * 16];
        int bi = redi[tid * 16];
#pragma unroll
        for (int t = 1; t < 16; t++) {
            float d = redd[tid * 16 + t];
            int ii = redi[tid * 16 + t];
            if (d < bd || (d == bd && ii < bi)) { bd = d; bi = ii; }
        }
        int b = bm + tid;
        g_codes[b * SS + s] = bi;
        atomicAdd(&g_counts[s * KC + bi], 1);
    }
}

// ---------------- gather quantized + write codes ----------------------------
__global__ void gather_pack_kernel(const float* __restrict__ cb,
                                   float* __restrict__ outq,
                                   float* __restrict__ outc) {
    int b = blockIdx.x;
    int g = threadIdx.x >> 5;       // split
    int lane = threadIdx.x & 31;
    int code = g_codes[b * SS + g];
    const float4* src = (const float4*)(cb + ((size_t)(g * KC + code)) * DD);
    float4* dst = (float4*)(outq + (size_t)b * SD + g * DD);
    dst[lane] = src[lane];
    dst[lane + 32] = src[lane + 32];
    if (lane == 0) outc[b * SS + g] = (float)code;
}

// ---------------- perplexity ------------------------------------------------
__global__ void perp_split_kernel() {
    int s = blockIdx.x;
    int tid = threadIdx.x;  // 256
    float sum = 0.0f;
    for (int k = tid; k < KC; k += 256) {
        float p = (float)g_counts[s * KC + k] * (1.0f / (float)BN);
        sum += p * logf(p + 1e-10f);
    }
#pragma unroll
    for (int o = 16; o; o >>= 1) sum += __shfl_xor_sync(0xFFFFFFFFu, sum, o);
    __shared__ float red[8];
    if ((tid & 31) == 0) red[tid >> 5] = sum;
    __syncthreads();
    if (tid == 0) {
        float t = 0.0f;
#pragma unroll
        for (int w = 0; w < 8; w++) t += red[w];
        g_perp[s] = expf(-t);
    }
}

__global__ void finalize_kernel(float* __restrict__ out_perp) {
    float t = 0.0f;
#pragma unroll
    for (int s = 0; s < SS; s++) t += g_perp[s];
    out_perp[0] = t / (float)SS;
}

// ---------------- launch ----------------------------------------------------
extern "C" void kernel_launch(void* const* d_in, const int* in_sizes, int n_in,
                              void* d_out, int out_size) {
    (void)in_sizes; (void)n_in; (void)out_size;
    const float* x     = (const float*)d_in[0];
    const float* enc_w = (const float*)d_in[1];
    const float* enc_b = (const float*)d_in[2];
    const float* cb    = (const float*)d_in[3];
    const float* dec_w = (const float*)d_in[4];
    const float* dec_b = (const float*)d_in[5];

    float* out = (float*)d_out;
    float* out_recon = out;                                  // [4096,2048]
    float* out_quant = out + (size_t)BN * SD;                // [4096,2048]
    float* out_codes = out + (size_t)2 * BN * SD;            // [4096,8]
    float* out_perp  = out_codes + (size_t)BN * SS;          // [1]

    void *pz, *pzsq, *pesq;
    cudaGetSymbolAddress(&pz, g_z);
    cudaGetSymbolAddress(&pzsq, g_zsq);
    cudaGetSymbolAddress(&pesq, g_esq);

    // dynamic smem for dist kernel: Zs + Bsm + Es
    const int DSM = (DD * 128 + 8 * 128 + 128) * (int)sizeof(float);
    cudaFuncSetAttribute(dist_argmin_kernel,
                         cudaFuncAttributeMaxDynamicSharedMemorySize, DSM);

    zero_counts_kernel<<<64, 1024>>>();

    // z = x @ enc_w^T + enc_b
    sgemm_tn<<<dim3(SD / 128, BN / 128), 256>>>(x, enc_w, enc_b, (float*)pz,
                                                BN, SD, IND);
    // per-(b,s) ||z||^2 and per-(s,k) ||e||^2
    rowsumsq_kernel<<<(BN * SS) / 8, 256>>>((const float*)pz, (float*)pzsq, BN * SS);
    rowsumsq_kernel<<<(SS * KC) / 8, 256>>>(cb, (float*)pesq, SS * KC);

    // fused distances + argmin + histogram
    dist_argmin_kernel<<<dim3(BN / 128, SS), 256, DSM>>>(cb);

    // gather quantized + codes
    gather_pack_kernel<<<BN, 256>>>(cb, out_quant, out_codes);

    // x_recon = quantized @ dec_w^T + dec_b
    sgemm_tn<<<dim3(IND / 128, BN / 128), 256>>>(out_quant, dec_w, dec_b,
                                                 out_recon, BN, IND, SD);

    perp_split_kernel<<<SS, 256>>>();
    finalize_kernel<<<1, 1>>>(out_perp);
}